// round 11
// baseline (speedup 1.0000x reference)
#include <cuda_runtime.h>
#include <cuda_fp16.h>
#include <cstdint>

// RGCN basis layer, scatter-first ordering, fused accumulate+GEMM:
//   agg[v, b, :] = sum_{e: dst=v} (w_comp[etype_e, b] * norm_e) * h[src_e]
//   out = relu( [agg | h] @ [W0;W1;W2;W3;loop_w] + bias )
// Stages:
//   prep:   h->fp16, Wh fp16 n-major stack, zero counts+total
//   hist:   per-dst counts + per-edge rank (4 edges/thread)
//   scan:   block-local exclusive scan + atomic block base
//   bucket: ONE 16B record {src, c01h, c23h} per edge (8 edges/thread)
//   fused:  per 128-node tile: phase1 edge accumulation -> A smem (fp16),
//           phase2 fp16 mma m16n8k16 GEMM vs Wh, bias+relu epilogue.

#define HD 128
#define NB 4
#define NNODES 50000
#define NEDGES 800000
#define NP 50176            // 392 * 128 = 196 * 256
#define NBLK 196
#define KTOT 640
#define SA 648              // A smem row stride in halves (1296B -> conflict-free)
#define SB 72               // B smem row stride in halves (144B -> conflict-free)

__device__ __half g_h16[(size_t)NP * HD];        // 12.8 MB
__device__ __half g_Wh[HD * KTOT];               // fp16 n-major weights

// CSR scratch
__device__ int  g_cnt[NP];
__device__ int  g_off[NP];
__device__ int  g_total;
__device__ int  g_rank[NEDGES];
__device__ int4 g_edge[NEDGES];    // {src, c01(half2), c23(half2), pad}

static __device__ __forceinline__ uint32_t smem_u32(const void* p) {
    uint32_t a;
    asm("{ .reg .u64 t; cvta.to.shared.u64 t, %1; cvt.u32.u64 %0, t; }" : "=r"(a) : "l"(p));
    return a;
}

#define CP_ASYNC8(sa, gp) \
    asm volatile("cp.async.ca.shared.global [%0], [%1], 8;" :: "r"(sa), "l"(gp))
#define CP_COMMIT() asm volatile("cp.async.commit_group;")

struct alignas(8) Half4 { __half2 lo, hi; };

static __device__ __forceinline__ int h2_as_int(__half2 h) { return *(int*)&h; }
static __device__ __forceinline__ __half2 int_as_h2(int i) { return *(__half2*)&i; }

// ---------------------------------------------------------------------------
// prep: h16 convert + weight stack + zero counts
// ---------------------------------------------------------------------------
__global__ __launch_bounds__(256) void prep_k(
    const float* __restrict__ h,
    const float* __restrict__ basis_w,
    const float* __restrict__ loop_w,
    int M)
{
    int idx = blockIdx.x * blockDim.x + threadIdx.x;

    if (idx < NP * 32) {
        int m = idx >> 5;
        float4 v = (m < M) ? *(const float4*)(h + (size_t)idx * 4)
                           : make_float4(0.f, 0.f, 0.f, 0.f);
        Half4 o;
        o.lo = __floats2half2_rn(v.x, v.y);
        o.hi = __floats2half2_rn(v.z, v.w);
        *(Half4*)(g_h16 + (size_t)idx * 4) = o;
    }
    if (idx < HD * KTOT) {          // Wh[n][k]
        int n = idx / KTOT;
        int k = idx - n * KTOT;
        float v;
        if (k < NB * HD) {
            int b = k >> 7, kk = k & 127;
            v = basis_w[(size_t)b * HD * HD + (size_t)kk * HD + n];
        } else {
            v = loop_w[(size_t)(k - NB * HD) * HD + n];
        }
        g_Wh[idx] = __float2half_rn(v);
    }
    if (idx < NP) g_cnt[idx] = 0;
    if (idx == 0) g_total = 0;
}

// ---------------------------------------------------------------------------
// hist: counts + per-edge rank, 4 edges/thread
// ---------------------------------------------------------------------------
__global__ __launch_bounds__(256) void hist_k(const int* __restrict__ dst, int E)
{
    int e0 = (blockIdx.x * blockDim.x + threadIdx.x) * 4;
    if (e0 + 3 < E) {
        int4 d = *(const int4*)(dst + e0);
        int r0 = atomicAdd(&g_cnt[d.x], 1);
        int r1 = atomicAdd(&g_cnt[d.y], 1);
        int r2 = atomicAdd(&g_cnt[d.z], 1);
        int r3 = atomicAdd(&g_cnt[d.w], 1);
        *(int4*)(g_rank + e0) = make_int4(r0, r1, r2, r3);
    } else {
        for (int e = e0; e < E; e++)
            g_rank[e] = atomicAdd(&g_cnt[dst[e]], 1);
    }
}

// ---------------------------------------------------------------------------
// scan: block-local exclusive scan; base via atomicAdd (order arbitrary)
// ---------------------------------------------------------------------------
__global__ __launch_bounds__(256) void scan_k()
{
    __shared__ int s[256];
    __shared__ int blockBase;
    int t = threadIdx.x;
    int gid = blockIdx.x * 256 + t;
    int v = g_cnt[gid];
    s[t] = v;
    __syncthreads();
    #pragma unroll
    for (int d = 1; d < 256; d <<= 1) {
        int x = (t >= d) ? s[t - d] : 0;
        __syncthreads();
        s[t] += x;
        __syncthreads();
    }
    if (t == 255) blockBase = atomicAdd(&g_total, s[255]);
    __syncthreads();
    g_off[gid] = blockBase + s[t] - v;
}

// ---------------------------------------------------------------------------
// bucket: one 16B record per edge, 8 edges/thread for MLP
// ---------------------------------------------------------------------------
__global__ __launch_bounds__(256) void bucket_k(
    const float* __restrict__ w_comp,
    const float* __restrict__ norm,
    const int* __restrict__ src,
    const int* __restrict__ dst,
    const int* __restrict__ etype,
    int E)
{
    int e0 = (blockIdx.x * blockDim.x + threadIdx.x) * 8;
    if (e0 + 7 < E) {
        #pragma unroll
        for (int g = 0; g < 2; g++) {
            int eb = e0 + g * 4;
            int4   d  = *(const int4*)(dst + eb);
            int4   sc = *(const int4*)(src + eb);
            int4   tt = *(const int4*)(etype + eb);
            float4 nm = *(const float4*)(norm + eb);
            int4   rk = *(const int4*)(g_rank + eb);
            int   dv[4] = {d.x, d.y, d.z, d.w};
            int   sv[4] = {sc.x, sc.y, sc.z, sc.w};
            int   tv[4] = {tt.x, tt.y, tt.z, tt.w};
            float nv[4] = {nm.x, nm.y, nm.z, nm.w};
            int   rv[4] = {rk.x, rk.y, rk.z, rk.w};
            #pragma unroll
            for (int j = 0; j < 4; j++) {
                const float* wr = w_comp + tv[j] * NB;
                __half2 c01 = __floats2half2_rn(wr[0] * nv[j], wr[1] * nv[j]);
                __half2 c23 = __floats2half2_rn(wr[2] * nv[j], wr[3] * nv[j]);
                g_edge[g_off[dv[j]] + rv[j]] =
                    make_int4(sv[j], h2_as_int(c01), h2_as_int(c23), 0);
            }
        }
    } else {
        for (int e = e0; e < E; e++) {
            int dd = dst[e];
            const float* wr = w_comp + etype[e] * NB;
            float nmv = norm[e];
            __half2 c01 = __floats2half2_rn(wr[0] * nmv, wr[1] * nmv);
            __half2 c23 = __floats2half2_rn(wr[2] * nmv, wr[3] * nmv);
            g_edge[g_off[dd] + g_rank[e]] =
                make_int4(src[e], h2_as_int(c01), h2_as_int(c23), 0);
        }
    }
}

// ---------------------------------------------------------------------------
// fused: 512 threads per 128-node tile.
// Phase 1: 16 warps x 8 nodes: edge accumulation -> A smem [128][SA] fp16
//          (cols 0..511 = agg, cols 512..639 = h16 copy).
// Phase 2: fp16 mma m16n8k16: [128 x 640] @ Wh^T -> out, bias+relu.
// ---------------------------------------------------------------------------
#define A_BYTES   (128 * SA * 2)            // 165888
#define B_STAGE   (128 * SB * 2)            // 18432
#define SMEM_TOT  (A_BYTES + 2 * B_STAGE)   // 202752

__global__ __launch_bounds__(512, 1) void fused_k(
    const float* __restrict__ bias,
    float* __restrict__ out,
    int M)
{
    extern __shared__ __half smh[];
    __half* As = smh;                  // [128][SA]
    __half* Bs = smh + 128 * SA;       // 2 stages of [128][SB]

    const int tid  = threadIdx.x;
    const int m0   = blockIdx.x * 128;
    const int lane = tid & 31;
    const int w    = tid >> 5;         // 0..15

    // ================= Phase 1: edge accumulation into As =================
    const __half* Hl = g_h16 + lane * 4;
    #pragma unroll 1
    for (int j = 0; j < 8; j++) {
        int r = w * 8 + j;             // block row
        int v = m0 + r;
        int base = g_off[v];
        int deg  = g_cnt[v];

        float4 a0 = {0.f, 0.f, 0.f, 0.f};
        float4 a1 = a0, a2 = a0, a3 = a0;

        int i = 0;
        for (; i + 4 <= deg; i += 4) {
            int4 r0 = g_edge[base + i];
            int4 r1 = g_edge[base + i + 1];
            int4 r2 = g_edge[base + i + 2];
            int4 r3 = g_edge[base + i + 3];
            Half4 hv0 = *(const Half4*)(Hl + (size_t)r0.x * HD);
            Half4 hv1 = *(const Half4*)(Hl + (size_t)r1.x * HD);
            Half4 hv2 = *(const Half4*)(Hl + (size_t)r2.x * HD);
            Half4 hv3 = *(const Half4*)(Hl + (size_t)r3.x * HD);
            #pragma unroll
            for (int q = 0; q < 4; q++) {
                int4 rr = (q == 0) ? r0 : (q == 1) ? r1 : (q == 2) ? r2 : r3;
                Half4 hh = (q == 0) ? hv0 : (q == 1) ? hv1 : (q == 2) ? hv2 : hv3;
                float2 c01 = __half22float2(int_as_h2(rr.y));
                float2 c23 = __half22float2(int_as_h2(rr.z));
                float2 lo = __half22float2(hh.lo), hi = __half22float2(hh.hi);
                a0.x += c01.x * lo.x; a0.y += c01.x * lo.y; a0.z += c01.x * hi.x; a0.w += c01.x * hi.y;
                a1.x += c01.y * lo.x; a1.y += c01.y * lo.y; a1.z += c01.y * hi.x; a1.w += c01.y * hi.y;
                a2.x += c23.x * lo.x; a2.y += c23.x * lo.y; a2.z += c23.x * hi.x; a2.w += c23.x * hi.y;
                a3.x += c23.y * lo.x; a3.y += c23.y * lo.y; a3.z += c23.y * hi.x; a3.w += c23.y * hi.y;
            }
        }
        for (; i < deg; i++) {
            int4 rr = g_edge[base + i];
            Half4 hh = *(const Half4*)(Hl + (size_t)rr.x * HD);
            float2 c01 = __half22float2(int_as_h2(rr.y));
            float2 c23 = __half22float2(int_as_h2(rr.z));
            float2 lo = __half22float2(hh.lo), hi = __half22float2(hh.hi);
            a0.x += c01.x * lo.x; a0.y += c01.x * lo.y; a0.z += c01.x * hi.x; a0.w += c01.x * hi.y;
            a1.x += c01.y * lo.x; a1.y += c01.y * lo.y; a1.z += c01.y * hi.x; a1.w += c01.y * hi.y;
            a2.x += c23.x * lo.x; a2.y += c23.x * lo.y; a2.z += c23.x * hi.x; a2.w += c23.x * hi.y;
            a3.x += c23.y * lo.x; a3.y += c23.y * lo.y; a3.z += c23.y * hi.x; a3.w += c23.y * hi.y;
        }

        __half* ap = As + r * SA + lane * 4;
        Half4 o;
        o.lo = __floats2half2_rn(a0.x, a0.y); o.hi = __floats2half2_rn(a0.z, a0.w);
        *(Half4*)(ap + 0)   = o;
        o.lo = __floats2half2_rn(a1.x, a1.y); o.hi = __floats2half2_rn(a1.z, a1.w);
        *(Half4*)(ap + 128) = o;
        o.lo = __floats2half2_rn(a2.x, a2.y); o.hi = __floats2half2_rn(a2.z, a2.w);
        *(Half4*)(ap + 256) = o;
        o.lo = __floats2half2_rn(a3.x, a3.y); o.hi = __floats2half2_rn(a3.z, a3.w);
        *(Half4*)(ap + 384) = o;
        // h16 copy into cols 512..639
        *(Half4*)(ap + 512) = *(const Half4*)(g_h16 + (size_t)v * HD + lane * 4);
    }

    // ================= Phase 2: GEMM =================
    const int wm = w & 3;              // 32-row m slice
    const int wn = w >> 2;             // 32-col n slice

    // B fill: 4 cp.async 8B per thread per chunk
    uint32_t bsBase = smem_u32(Bs);
    auto fill = [&](int kc, int s) {
        uint32_t sb = bsBase + (uint32_t)s * B_STAGE;
        #pragma unroll
        for (int i = 0; i < 4; i++) {
            int idx = tid + 512 * i;
            int n = idx >> 4;
            int q = idx & 15;
            CP_ASYNC8(sb + (uint32_t)(n * SB + q * 4) * 2,
                      g_Wh + (size_t)n * KTOT + kc * 64 + q * 4);
        }
        CP_COMMIT();
    };

    const int arow  = (lane & 7) + ((lane >> 3) & 1) * 8;
    const int akoff = (lane & 16) ? 8 : 0;
    const int brow  = (lane & 7) + ((lane & 16) ? 8 : 0);
    const int bkoff = (lane & 8) ? 8 : 0;

    uint32_t aAddr[2], bAddr[2];
    #pragma unroll
    for (int mt = 0; mt < 2; mt++)
        aAddr[mt] = smem_u32(As + (wm * 32 + mt * 16 + arow) * SA + akoff);
    #pragma unroll
    for (int p = 0; p < 2; p++)
        bAddr[p] = smem_u32(Bs + (wn * 32 + p * 16 + brow) * SB + bkoff);

    float acc[2][4][4];
    #pragma unroll
    for (int mt = 0; mt < 2; mt++)
        #pragma unroll
        for (int nt = 0; nt < 4; nt++)
            #pragma unroll
            for (int q = 0; q < 4; q++) acc[mt][nt][q] = 0.f;

    fill(0, 0);
    fill(1, 1);

    for (int kc = 0; kc < 10; kc++) {
        int s = kc & 1;
        if (kc == 9) { asm volatile("cp.async.wait_group 0;"); }
        else         { asm volatile("cp.async.wait_group 1;"); }
        __syncthreads();   // first iter also publishes phase-1 As writes

        uint32_t aOff = (uint32_t)(kc * 64) * 2;
        uint32_t bOff = (uint32_t)s * B_STAGE;
        #pragma unroll
        for (int k0 = 0; k0 < 64; k0 += 16) {
            uint32_t a[2][4], b[2][4];
            #pragma unroll
            for (int mt = 0; mt < 2; mt++)
                asm volatile("ldmatrix.sync.aligned.m8n8.x4.shared.b16 {%0,%1,%2,%3}, [%4];"
                             : "=r"(a[mt][0]), "=r"(a[mt][1]), "=r"(a[mt][2]), "=r"(a[mt][3])
                             : "r"(aAddr[mt] + aOff + k0 * 2));
            #pragma unroll
            for (int p = 0; p < 2; p++)
                asm volatile("ldmatrix.sync.aligned.m8n8.x4.shared.b16 {%0,%1,%2,%3}, [%4];"
                             : "=r"(b[p][0]), "=r"(b[p][1]), "=r"(b[p][2]), "=r"(b[p][3])
                             : "r"(bAddr[p] + bOff + k0 * 2));
            #pragma unroll
            for (int mt = 0; mt < 2; mt++)
                #pragma unroll
                for (int nt = 0; nt < 4; nt++) {
                    int p = nt >> 1, q = (nt & 1) * 2;
                    asm volatile(
                        "mma.sync.aligned.m16n8k16.row.col.f32.f16.f16.f32 "
                        "{%0,%1,%2,%3}, {%4,%5,%6,%7}, {%8,%9}, {%0,%1,%2,%3};"
                        : "+f"(acc[mt][nt][0]), "+f"(acc[mt][nt][1]),
                          "+f"(acc[mt][nt][2]), "+f"(acc[mt][nt][3])
                        : "r"(a[mt][0]), "r"(a[mt][1]), "r"(a[mt][2]), "r"(a[mt][3]),
                          "r"(b[p][q]), "r"(b[p][q + 1]));
                }
        }
        __syncthreads();
        if (kc + 2 < 10) fill(kc + 2, s);
    }

    // ---- epilogue: bias + relu ----
    const int rbase = lane >> 2;
    const int col2  = (lane & 3) * 2;
    #pragma unroll
    for (int mt = 0; mt < 2; mt++) {
        #pragma unroll
        for (int hh = 0; hh < 2; hh++) {
            int gm = m0 + wm * 32 + mt * 16 + rbase + hh * 8;
            if (gm >= M) continue;
            #pragma unroll
            for (int nt = 0; nt < 4; nt++) {
                int gn = wn * 32 + nt * 8 + col2;
                float2 o;
                o.x = fmaxf(acc[mt][nt][hh * 2]     + bias[gn],     0.f);
                o.y = fmaxf(acc[mt][nt][hh * 2 + 1] + bias[gn + 1], 0.f);
                *(float2*)(out + (size_t)gm * HD + gn) = o;
            }
        }
    }
}

extern "C" void kernel_launch(void* const* d_in, const int* in_sizes, int n_in,
                              void* d_out, int out_size)
{
    const float* h       = (const float*)d_in[0];
    const float* norm    = (const float*)d_in[1];
    const float* basis_w = (const float*)d_in[2];
    const float* w_comp  = (const float*)d_in[3];
    const float* loop_w  = (const float*)d_in[4];
    const float* bias    = (const float*)d_in[5];
    const int*   src     = (const int*)d_in[6];
    const int*   dst     = (const int*)d_in[7];
    const int*   etype   = (const int*)d_in[8];
    float* out = (float*)d_out;

    int M = in_sizes[0] / HD;   // 50000
    int E = in_sizes[6];        // 800000

    cudaFuncSetAttribute(fused_k, cudaFuncAttributeMaxDynamicSharedMemorySize, SMEM_TOT);

    prep_k<<<(NP * 32 + 255) / 256, 256>>>(h, basis_w, loop_w, M);
    hist_k<<<((E + 3) / 4 + 255) / 256, 256>>>(dst, E);
    scan_k<<<NBLK, 256>>>();
    bucket_k<<<((E + 7) / 8 + 255) / 256, 256>>>(w_comp, norm, src, dst, etype, E);
    fused_k<<<NP / 128, 512, SMEM_TOT>>>(bias, out, M);
}

// round 12
// speedup vs baseline: 1.0962x; 1.0962x over previous
#include <cuda_runtime.h>
#include <cuda_fp16.h>
#include <cstdint>

// RGCN basis layer, scatter-first ordering (round-10 structure, gemm2 retiled):
//   agg[v, b, :] = sum_{e: dst=v} (w_comp[etype_e, b] * norm_e) * h[src_e]
//   out = relu( [agg | h] @ [W0;W1;W2;W3;loop_w] + bias )
// Stages:
//   prep:   h->fp16, Wh fp16 n-major stack, zero counts+total
//   hist:   per-dst counts + per-edge rank (4 edges/thread)
//   scan:   block-local exclusive scan + atomic block base
//   bucket: ONE 16B record {src, c01h, c23h} per edge (8 edges/thread)
//   accum:  warp/dst register accumulation -> agg fp16 (4-edge unroll)
//   gemm2:  fp16 mma m16n8k16, m-tile 64, 3-stage cp.async, 2 blocks/SM

#define HD 128
#define NB 4
#define NNODES 50000
#define NEDGES 800000
#define NP 50176            // 392 * 128 = 784 * 64
#define NBLK 196
#define KTOT 640
#define SB 72               // smem row stride in halves (144B) -> conflict-free

__device__ __half g_h16[(size_t)NP * HD];        // 12.8 MB
__device__ __half g_agg[(size_t)NP * 512];       // 51.4 MB
__device__ __half g_Wh[HD * KTOT];               // fp16 n-major weights

// CSR scratch
__device__ int  g_cnt[NP];
__device__ int  g_off[NP];
__device__ int  g_total;
__device__ int  g_rank[NEDGES];
__device__ int4 g_edge[NEDGES];    // {src, c01(half2), c23(half2), pad}

static __device__ __forceinline__ uint32_t smem_u32(const void* p) {
    uint32_t a;
    asm("{ .reg .u64 t; cvta.to.shared.u64 t, %1; cvt.u32.u64 %0, t; }" : "=r"(a) : "l"(p));
    return a;
}

#define CP_ASYNC8(sa, gp) \
    asm volatile("cp.async.ca.shared.global [%0], [%1], 8;" :: "r"(sa), "l"(gp))
#define CP_COMMIT() asm volatile("cp.async.commit_group;")

struct alignas(8) Half4 { __half2 lo, hi; };

static __device__ __forceinline__ int h2_as_int(__half2 h) { return *(int*)&h; }
static __device__ __forceinline__ __half2 int_as_h2(int i) { return *(__half2*)&i; }

// ---------------------------------------------------------------------------
// prep: h16 convert + weight stack + zero counts
// ---------------------------------------------------------------------------
__global__ __launch_bounds__(256) void prep_k(
    const float* __restrict__ h,
    const float* __restrict__ basis_w,
    const float* __restrict__ loop_w,
    int M)
{
    int idx = blockIdx.x * blockDim.x + threadIdx.x;

    if (idx < NP * 32) {
        int m = idx >> 5;
        float4 v = (m < M) ? *(const float4*)(h + (size_t)idx * 4)
                           : make_float4(0.f, 0.f, 0.f, 0.f);
        Half4 o;
        o.lo = __floats2half2_rn(v.x, v.y);
        o.hi = __floats2half2_rn(v.z, v.w);
        *(Half4*)(g_h16 + (size_t)idx * 4) = o;
    }
    if (idx < HD * KTOT) {          // Wh[n][k]
        int n = idx / KTOT;
        int k = idx - n * KTOT;
        float v;
        if (k < NB * HD) {
            int b = k >> 7, kk = k & 127;
            v = basis_w[(size_t)b * HD * HD + (size_t)kk * HD + n];
        } else {
            v = loop_w[(size_t)(k - NB * HD) * HD + n];
        }
        g_Wh[idx] = __float2half_rn(v);
    }
    if (idx < NP) g_cnt[idx] = 0;
    if (idx == 0) g_total = 0;
}

// ---------------------------------------------------------------------------
// hist: counts + per-edge rank, 4 edges/thread
// ---------------------------------------------------------------------------
__global__ __launch_bounds__(256) void hist_k(const int* __restrict__ dst, int E)
{
    int e0 = (blockIdx.x * blockDim.x + threadIdx.x) * 4;
    if (e0 + 3 < E) {
        int4 d = *(const int4*)(dst + e0);
        int r0 = atomicAdd(&g_cnt[d.x], 1);
        int r1 = atomicAdd(&g_cnt[d.y], 1);
        int r2 = atomicAdd(&g_cnt[d.z], 1);
        int r3 = atomicAdd(&g_cnt[d.w], 1);
        *(int4*)(g_rank + e0) = make_int4(r0, r1, r2, r3);
    } else {
        for (int e = e0; e < E; e++)
            g_rank[e] = atomicAdd(&g_cnt[dst[e]], 1);
    }
}

// ---------------------------------------------------------------------------
// scan: block-local exclusive scan; base via atomicAdd (order arbitrary)
// ---------------------------------------------------------------------------
__global__ __launch_bounds__(256) void scan_k()
{
    __shared__ int s[256];
    __shared__ int blockBase;
    int t = threadIdx.x;
    int gid = blockIdx.x * 256 + t;
    int v = g_cnt[gid];
    s[t] = v;
    __syncthreads();
    #pragma unroll
    for (int d = 1; d < 256; d <<= 1) {
        int x = (t >= d) ? s[t - d] : 0;
        __syncthreads();
        s[t] += x;
        __syncthreads();
    }
    if (t == 255) blockBase = atomicAdd(&g_total, s[255]);
    __syncthreads();
    g_off[gid] = blockBase + s[t] - v;
}

// ---------------------------------------------------------------------------
// bucket: one 16B record per edge, 8 edges/thread for MLP
// ---------------------------------------------------------------------------
__global__ __launch_bounds__(256) void bucket_k(
    const float* __restrict__ w_comp,
    const float* __restrict__ norm,
    const int* __restrict__ src,
    const int* __restrict__ dst,
    const int* __restrict__ etype,
    int E)
{
    int e0 = (blockIdx.x * blockDim.x + threadIdx.x) * 8;
    if (e0 + 7 < E) {
        #pragma unroll
        for (int g = 0; g < 2; g++) {
            int eb = e0 + g * 4;
            int4   d  = *(const int4*)(dst + eb);
            int4   sc = *(const int4*)(src + eb);
            int4   tt = *(const int4*)(etype + eb);
            float4 nm = *(const float4*)(norm + eb);
            int4   rk = *(const int4*)(g_rank + eb);
            int   dv[4] = {d.x, d.y, d.z, d.w};
            int   sv[4] = {sc.x, sc.y, sc.z, sc.w};
            int   tv[4] = {tt.x, tt.y, tt.z, tt.w};
            float nv[4] = {nm.x, nm.y, nm.z, nm.w};
            int   rv[4] = {rk.x, rk.y, rk.z, rk.w};
            #pragma unroll
            for (int j = 0; j < 4; j++) {
                const float* wr = w_comp + tv[j] * NB;
                __half2 c01 = __floats2half2_rn(wr[0] * nv[j], wr[1] * nv[j]);
                __half2 c23 = __floats2half2_rn(wr[2] * nv[j], wr[3] * nv[j]);
                g_edge[g_off[dv[j]] + rv[j]] =
                    make_int4(sv[j], h2_as_int(c01), h2_as_int(c23), 0);
            }
        }
    } else {
        for (int e = e0; e < E; e++) {
            int dd = dst[e];
            const float* wr = w_comp + etype[e] * NB;
            float nmv = norm[e];
            __half2 c01 = __floats2half2_rn(wr[0] * nmv, wr[1] * nmv);
            __half2 c23 = __floats2half2_rn(wr[2] * nmv, wr[3] * nmv);
            g_edge[g_off[dd] + g_rank[e]] =
                make_int4(src[e], h2_as_int(c01), h2_as_int(c23), 0);
        }
    }
}

// ---------------------------------------------------------------------------
// accum: warp per dst node; 16 fp32 acc regs/lane; 4-edge unroll (MLP 4).
// ---------------------------------------------------------------------------
__global__ __launch_bounds__(256) void accum_k()
{
    int v    = (blockIdx.x * blockDim.x + threadIdx.x) >> 5;
    int lane = threadIdx.x & 31;
    if (v >= NP) return;

    int base = g_off[v];
    int deg  = g_cnt[v];

    float4 a0 = {0.f, 0.f, 0.f, 0.f};
    float4 a1 = a0, a2 = a0, a3 = a0;

    const __half* Hl = g_h16 + lane * 4;

    int i = 0;
    for (; i + 4 <= deg; i += 4) {
        int4 r0 = g_edge[base + i];
        int4 r1 = g_edge[base + i + 1];
        int4 r2 = g_edge[base + i + 2];
        int4 r3 = g_edge[base + i + 3];
        Half4 hv0 = *(const Half4*)(Hl + (size_t)r0.x * HD);
        Half4 hv1 = *(const Half4*)(Hl + (size_t)r1.x * HD);
        Half4 hv2 = *(const Half4*)(Hl + (size_t)r2.x * HD);
        Half4 hv3 = *(const Half4*)(Hl + (size_t)r3.x * HD);
        #pragma unroll
        for (int j = 0; j < 4; j++) {
            int4 rr = (j == 0) ? r0 : (j == 1) ? r1 : (j == 2) ? r2 : r3;
            Half4 hh = (j == 0) ? hv0 : (j == 1) ? hv1 : (j == 2) ? hv2 : hv3;
            float2 c01 = __half22float2(int_as_h2(rr.y));
            float2 c23 = __half22float2(int_as_h2(rr.z));
            float2 lo = __half22float2(hh.lo), hi = __half22float2(hh.hi);
            a0.x += c01.x * lo.x; a0.y += c01.x * lo.y; a0.z += c01.x * hi.x; a0.w += c01.x * hi.y;
            a1.x += c01.y * lo.x; a1.y += c01.y * lo.y; a1.z += c01.y * hi.x; a1.w += c01.y * hi.y;
            a2.x += c23.x * lo.x; a2.y += c23.x * lo.y; a2.z += c23.x * hi.x; a2.w += c23.x * hi.y;
            a3.x += c23.y * lo.x; a3.y += c23.y * lo.y; a3.z += c23.y * hi.x; a3.w += c23.y * hi.y;
        }
    }
    for (; i < deg; i++) {
        int4 rr = g_edge[base + i];
        Half4 hh = *(const Half4*)(Hl + (size_t)rr.x * HD);
        float2 c01 = __half22float2(int_as_h2(rr.y));
        float2 c23 = __half22float2(int_as_h2(rr.z));
        float2 lo = __half22float2(hh.lo), hi = __half22float2(hh.hi);
        a0.x += c01.x * lo.x; a0.y += c01.x * lo.y; a0.z += c01.x * hi.x; a0.w += c01.x * hi.y;
        a1.x += c01.y * lo.x; a1.y += c01.y * lo.y; a1.z += c01.y * hi.x; a1.w += c01.y * hi.y;
        a2.x += c23.x * lo.x; a2.y += c23.x * lo.y; a2.z += c23.x * hi.x; a2.w += c23.x * hi.y;
        a3.x += c23.y * lo.x; a3.y += c23.y * lo.y; a3.z += c23.y * hi.x; a3.w += c23.y * hi.y;
    }

    __half* ap = g_agg + (size_t)v * 512 + lane * 4;
    Half4 o;
    o.lo = __floats2half2_rn(a0.x, a0.y); o.hi = __floats2half2_rn(a0.z, a0.w);
    *(Half4*)(ap + 0)   = o;
    o.lo = __floats2half2_rn(a1.x, a1.y); o.hi = __floats2half2_rn(a1.z, a1.w);
    *(Half4*)(ap + 128) = o;
    o.lo = __floats2half2_rn(a2.x, a2.y); o.hi = __floats2half2_rn(a2.z, a2.w);
    *(Half4*)(ap + 256) = o;
    o.lo = __floats2half2_rn(a3.x, a3.y); o.hi = __floats2half2_rn(a3.z, a3.w);
    *(Half4*)(ap + 384) = o;
}

// ---------------------------------------------------------------------------
// gemm2: fp16 mma m16n8k16, m-tile 64 x n 128, K=640 in 64-chunks,
// 3-stage cp.async, 2 blocks/SM. 8 warps = 2m x 4n; warp tile 32m x 32n.
// ---------------------------------------------------------------------------
#define MT 64
#define STAGE_HALVES ((MT + 128) * SB)             // A(64 rows) + B(128 rows)
#define STAGE_BYTES  (STAGE_HALVES * 2)            // 27648
#define SMEM_BYTES   (3 * STAGE_BYTES)             // 82944

__global__ __launch_bounds__(256, 2) void gemm2_k(
    const float* __restrict__ bias,
    float* __restrict__ out,
    int M)
{
    extern __shared__ __half smh[];

    const int tid  = threadIdx.x;
    const int m0   = blockIdx.x * MT;
    const int lane = tid & 31;
    const int w    = tid >> 5;
    const int wm   = w & 1;     // 2 m-slices of 32
    const int wn   = w >> 1;    // 4 n-slices of 32

    uint32_t smBase = smem_u32(smh);

    // fill one 64-k chunk into stage s: A 64 rows, B 128 rows
    auto fill = [&](int kc, int s) {
        uint32_t sa = smBase + (uint32_t)s * STAGE_BYTES;
        uint32_t sb = sa + (uint32_t)(MT * SB) * 2;
        // A: 64 rows x 16 quads = 1024 -> 4 per thread
        if (kc < 8) {
            #pragma unroll
            for (int i = 0; i < 4; i++) {
                int idx = tid + 256 * i;
                int r = idx >> 4, q = idx & 15;
                CP_ASYNC8(sa + (uint32_t)(r * SB + q * 4) * 2,
                          g_agg + (size_t)(m0 + r) * 512 + kc * 64 + q * 4);
            }
        } else {
            #pragma unroll
            for (int i = 0; i < 4; i++) {
                int idx = tid + 256 * i;
                int r = idx >> 4, q = idx & 15;
                CP_ASYNC8(sa + (uint32_t)(r * SB + q * 4) * 2,
                          g_h16 + (size_t)(m0 + r) * HD + (kc * 64 - 512) + q * 4);
            }
        }
        // B: 128 rows x 16 quads = 2048 -> 8 per thread
        #pragma unroll
        for (int i = 0; i < 8; i++) {
            int idx = tid + 256 * i;
            int n = idx >> 4, q = idx & 15;
            CP_ASYNC8(sb + (uint32_t)(n * SB + q * 4) * 2,
                      g_Wh + (size_t)n * KTOT + kc * 64 + q * 4);
        }
        CP_COMMIT();
    };

    const int arow  = (lane & 7) + ((lane >> 3) & 1) * 8;
    const int akoff = (lane & 16) ? 8 : 0;
    const int brow  = (lane & 7) + ((lane & 16) ? 8 : 0);
    const int bkoff = (lane & 8) ? 8 : 0;

    // stage-0 base addresses; add s*STAGE_BYTES at use
    uint32_t aAddr[2], bAddr[2];
    #pragma unroll
    for (int mt = 0; mt < 2; mt++)
        aAddr[mt] = smBase + (uint32_t)((wm * 32 + mt * 16 + arow) * SB + akoff) * 2;
    #pragma unroll
    for (int p = 0; p < 2; p++)
        bAddr[p] = smBase + (uint32_t)(MT * SB + (wn * 32 + p * 16 + brow) * SB + bkoff) * 2;

    float acc[2][4][4];
    #pragma unroll
    for (int mt = 0; mt < 2; mt++)
        #pragma unroll
        for (int nt = 0; nt < 4; nt++)
            #pragma unroll
            for (int q = 0; q < 4; q++) acc[mt][nt][q] = 0.f;

    fill(0, 0);
    fill(1, 1);
    fill(2, 2);

    for (int kc = 0; kc < 10; kc++) {
        int s = kc % 3;
        if (kc < 8)       { asm volatile("cp.async.wait_group 2;"); }
        else if (kc == 8) { asm volatile("cp.async.wait_group 1;"); }
        else              { asm volatile("cp.async.wait_group 0;"); }
        __syncthreads();

        uint32_t soff = (uint32_t)s * STAGE_BYTES;
        #pragma unroll
        for (int k0 = 0; k0 < 64; k0 += 16) {
            uint32_t a[2][4], b[2][4];
            #pragma unroll
            for (int mt = 0; mt < 2; mt++)
                asm volatile("ldmatrix.sync.aligned.m8n8.x4.shared.b16 {%0,%1,%2,%3}, [%4];"
                             : "=r"(a[mt][0]), "=r"(a[mt][1]), "=r"(a[mt][2]), "=r"(a[mt][3])
                             : "r"(aAddr[mt] + soff + k0 * 2));
            #pragma unroll
            for (int p = 0; p < 2; p++)
                asm volatile("ldmatrix.sync.aligned.m8n8.x4.shared.b16 {%0,%1,%2,%3}, [%4];"
                             : "=r"(b[p][0]), "=r"(b[p][1]), "=r"(b[p][2]), "=r"(b[p][3])
                             : "r"(bAddr[p] + soff + k0 * 2));
            // b[p]: r0=b0(nt 2p), r1=b1(nt 2p), r2=b0(nt 2p+1), r3=b1(nt 2p+1)
            #pragma unroll
            for (int mt = 0; mt < 2; mt++)
                #pragma unroll
                for (int nt = 0; nt < 4; nt++) {
                    int p = nt >> 1, q = (nt & 1) * 2;
                    asm volatile(
                        "mma.sync.aligned.m16n8k16.row.col.f32.f16.f16.f32 "
                        "{%0,%1,%2,%3}, {%4,%5,%6,%7}, {%8,%9}, {%0,%1,%2,%3};"
                        : "+f"(acc[mt][nt][0]), "+f"(acc[mt][nt][1]),
                          "+f"(acc[mt][nt][2]), "+f"(acc[mt][nt][3])
                        : "r"(a[mt][0]), "r"(a[mt][1]), "r"(a[mt][2]), "r"(a[mt][3]),
                          "r"(b[p][q]), "r"(b[p][q + 1]));
                }
        }
        __syncthreads();
        if (kc + 3 < 10) fill(kc + 3, s);
    }

    // ---- epilogue: bias + relu ----
    const int rbase = lane >> 2;
    const int col2  = (lane & 3) * 2;
    #pragma unroll
    for (int mt = 0; mt < 2; mt++) {
        #pragma unroll
        for (int hh = 0; hh < 2; hh++) {
            int gm = m0 + wm * 32 + mt * 16 + rbase + hh * 8;
            if (gm >= M) continue;
            #pragma unroll
            for (int nt = 0; nt < 4; nt++) {
                int gn = wn * 32 + nt * 8 + col2;
                float2 o;
                o.x = fmaxf(acc[mt][nt][hh * 2]     + bias[gn],     0.f);
                o.y = fmaxf(acc[mt][nt][hh * 2 + 1] + bias[gn + 1], 0.f);
                *(float2*)(out + (size_t)gm * HD + gn) = o;
            }
        }
    }
}

extern "C" void kernel_launch(void* const* d_in, const int* in_sizes, int n_in,
                              void* d_out, int out_size)
{
    const float* h       = (const float*)d_in[0];
    const float* norm    = (const float*)d_in[1];
    const float* basis_w = (const float*)d_in[2];
    const float* w_comp  = (const float*)d_in[3];
    const float* loop_w  = (const float*)d_in[4];
    const float* bias    = (const float*)d_in[5];
    const int*   src     = (const int*)d_in[6];
    const int*   dst     = (const int*)d_in[7];
    const int*   etype   = (const int*)d_in[8];
    float* out = (float*)d_out;

    int M = in_sizes[0] / HD;   // 50000
    int E = in_sizes[6];        // 800000

    cudaFuncSetAttribute(gemm2_k, cudaFuncAttributeMaxDynamicSharedMemorySize, SMEM_BYTES);

    prep_k<<<(NP * 32 + 255) / 256, 256>>>(h, basis_w, loop_w, M);
    hist_k<<<((E + 3) / 4 + 255) / 256, 256>>>(dst, E);
    scan_k<<<NBLK, 256>>>();
    bucket_k<<<((E + 7) / 8 + 255) / 256, 256>>>(w_comp, norm, src, dst, etype, E);
    accum_k<<<(NP * 32 + 255) / 256, 256>>>();
    gemm2_k<<<NP / MT, 256, SMEM_BYTES>>>(bias, out, M);
}

// round 13
// speedup vs baseline: 1.1208x; 1.0224x over previous
#include <cuda_runtime.h>
#include <cuda_fp16.h>
#include <cstdint>

// RGCN basis layer, scatter-first ordering (round-10 structure; gemm2 3-stage):
//   agg[v, b, :] = sum_{e: dst=v} (w_comp[etype_e, b] * norm_e) * h[src_e]
//   out = relu( [agg | h] @ [W0;W1;W2;W3;loop_w] + bias )
// Stages:
//   prep:   h->fp16, Wh fp16 n-major stack, zero counts+total
//   hist:   per-dst counts + per-edge rank (4 edges/thread)
//   scan:   block-local exclusive scan + atomic block base
//   bucket: ONE 16B record {src, c01h, c23h} per edge
//   accum:  warp/dst register accumulation -> agg fp16 (4-edge unroll)
//   gemm2:  fp16 mma m16n8k16, 128x128 tile, 3-stage cp.async, 2 blocks/SM

#define HD 128
#define NB 4
#define NNODES 50000
#define NEDGES 800000
#define NP 50176            // 392 * 128 = 196 * 256
#define NBLK 196
#define KTOT 640
#define SMSH 72             // smem row stride in halves (144B) -> conflict-free

__device__ __half g_h16[(size_t)NP * HD];        // 12.8 MB
__device__ __half g_agg[(size_t)NP * 512];       // 51.4 MB
__device__ __half g_Wh[HD * KTOT];               // fp16 n-major weights

// CSR scratch
__device__ int  g_cnt[NP];
__device__ int  g_off[NP];
__device__ int  g_total;
__device__ int  g_rank[NEDGES];
__device__ int4 g_edge[NEDGES];    // {src, c01(half2), c23(half2), pad}

static __device__ __forceinline__ uint32_t smem_u32(const void* p) {
    uint32_t a;
    asm("{ .reg .u64 t; cvta.to.shared.u64 t, %1; cvt.u32.u64 %0, t; }" : "=r"(a) : "l"(p));
    return a;
}

#define CP_ASYNC8(sa, gp) \
    asm volatile("cp.async.ca.shared.global [%0], [%1], 8;" :: "r"(sa), "l"(gp))
#define CP_COMMIT() asm volatile("cp.async.commit_group;")

struct alignas(8) Half4 { __half2 lo, hi; };

static __device__ __forceinline__ int h2_as_int(__half2 h) { return *(int*)&h; }
static __device__ __forceinline__ __half2 int_as_h2(int i) { return *(__half2*)&i; }

// ---------------------------------------------------------------------------
// prep: h16 convert + weight stack + zero counts
// ---------------------------------------------------------------------------
__global__ __launch_bounds__(256) void prep_k(
    const float* __restrict__ h,
    const float* __restrict__ basis_w,
    const float* __restrict__ loop_w,
    int M)
{
    int idx = blockIdx.x * blockDim.x + threadIdx.x;

    if (idx < NP * 32) {
        int m = idx >> 5;
        float4 v = (m < M) ? *(const float4*)(h + (size_t)idx * 4)
                           : make_float4(0.f, 0.f, 0.f, 0.f);
        Half4 o;
        o.lo = __floats2half2_rn(v.x, v.y);
        o.hi = __floats2half2_rn(v.z, v.w);
        *(Half4*)(g_h16 + (size_t)idx * 4) = o;
    }
    if (idx < HD * KTOT) {          // Wh[n][k]
        int n = idx / KTOT;
        int k = idx - n * KTOT;
        float v;
        if (k < NB * HD) {
            int b = k >> 7, kk = k & 127;
            v = basis_w[(size_t)b * HD * HD + (size_t)kk * HD + n];
        } else {
            v = loop_w[(size_t)(k - NB * HD) * HD + n];
        }
        g_Wh[idx] = __float2half_rn(v);
    }
    if (idx < NP) g_cnt[idx] = 0;
    if (idx == 0) g_total = 0;
}

// ---------------------------------------------------------------------------
// hist: counts + per-edge rank, 4 edges/thread
// ---------------------------------------------------------------------------
__global__ __launch_bounds__(256) void hist_k(const int* __restrict__ dst, int E)
{
    int e0 = (blockIdx.x * blockDim.x + threadIdx.x) * 4;
    if (e0 + 3 < E) {
        int4 d = *(const int4*)(dst + e0);
        int r0 = atomicAdd(&g_cnt[d.x], 1);
        int r1 = atomicAdd(&g_cnt[d.y], 1);
        int r2 = atomicAdd(&g_cnt[d.z], 1);
        int r3 = atomicAdd(&g_cnt[d.w], 1);
        *(int4*)(g_rank + e0) = make_int4(r0, r1, r2, r3);
    } else {
        for (int e = e0; e < E; e++)
            g_rank[e] = atomicAdd(&g_cnt[dst[e]], 1);
    }
}

// ---------------------------------------------------------------------------
// scan: block-local exclusive scan; base via atomicAdd (order arbitrary)
// ---------------------------------------------------------------------------
__global__ __launch_bounds__(256) void scan_k()
{
    __shared__ int s[256];
    __shared__ int blockBase;
    int t = threadIdx.x;
    int gid = blockIdx.x * 256 + t;
    int v = g_cnt[gid];
    s[t] = v;
    __syncthreads();
    #pragma unroll
    for (int d = 1; d < 256; d <<= 1) {
        int x = (t >= d) ? s[t - d] : 0;
        __syncthreads();
        s[t] += x;
        __syncthreads();
    }
    if (t == 255) blockBase = atomicAdd(&g_total, s[255]);
    __syncthreads();
    g_off[gid] = blockBase + s[t] - v;
}

// ---------------------------------------------------------------------------
// bucket: one 16B record per edge, single scattered STG.128
// ---------------------------------------------------------------------------
__global__ __launch_bounds__(256) void bucket_k(
    const float* __restrict__ w_comp,
    const float* __restrict__ norm,
    const int* __restrict__ src,
    const int* __restrict__ dst,
    const int* __restrict__ etype,
    int E)
{
    int e0 = (blockIdx.x * blockDim.x + threadIdx.x) * 4;
    if (e0 + 3 < E) {
        int4   d  = *(const int4*)(dst + e0);
        int4   sc = *(const int4*)(src + e0);
        int4   tt = *(const int4*)(etype + e0);
        float4 nm = *(const float4*)(norm + e0);
        int4   rk = *(const int4*)(g_rank + e0);
        int   dv[4] = {d.x, d.y, d.z, d.w};
        int   sv[4] = {sc.x, sc.y, sc.z, sc.w};
        int   tv[4] = {tt.x, tt.y, tt.z, tt.w};
        float nv[4] = {nm.x, nm.y, nm.z, nm.w};
        int   rv[4] = {rk.x, rk.y, rk.z, rk.w};
        #pragma unroll
        for (int j = 0; j < 4; j++) {
            const float* wr = w_comp + tv[j] * NB;
            __half2 c01 = __floats2half2_rn(wr[0] * nv[j], wr[1] * nv[j]);
            __half2 c23 = __floats2half2_rn(wr[2] * nv[j], wr[3] * nv[j]);
            g_edge[g_off[dv[j]] + rv[j]] =
                make_int4(sv[j], h2_as_int(c01), h2_as_int(c23), 0);
        }
    } else {
        for (int e = e0; e < E; e++) {
            int dd = dst[e];
            const float* wr = w_comp + etype[e] * NB;
            float nmv = norm[e];
            __half2 c01 = __floats2half2_rn(wr[0] * nmv, wr[1] * nmv);
            __half2 c23 = __floats2half2_rn(wr[2] * nmv, wr[3] * nmv);
            g_edge[g_off[dd] + g_rank[e]] =
                make_int4(src[e], h2_as_int(c01), h2_as_int(c23), 0);
        }
    }
}

// ---------------------------------------------------------------------------
// accum: warp per dst node; 16 fp32 acc regs/lane; 4-edge unroll (MLP 4).
// ---------------------------------------------------------------------------
__global__ __launch_bounds__(256) void accum_k()
{
    int v    = (blockIdx.x * blockDim.x + threadIdx.x) >> 5;
    int lane = threadIdx.x & 31;
    if (v >= NP) return;

    int base = g_off[v];
    int deg  = g_cnt[v];

    float4 a0 = {0.f, 0.f, 0.f, 0.f};
    float4 a1 = a0, a2 = a0, a3 = a0;

    const __half* Hl = g_h16 + lane * 4;

    int i = 0;
    for (; i + 4 <= deg; i += 4) {
        int4 r0 = g_edge[base + i];
        int4 r1 = g_edge[base + i + 1];
        int4 r2 = g_edge[base + i + 2];
        int4 r3 = g_edge[base + i + 3];
        Half4 hv0 = *(const Half4*)(Hl + (size_t)r0.x * HD);
        Half4 hv1 = *(const Half4*)(Hl + (size_t)r1.x * HD);
        Half4 hv2 = *(const Half4*)(Hl + (size_t)r2.x * HD);
        Half4 hv3 = *(const Half4*)(Hl + (size_t)r3.x * HD);
        #pragma unroll
        for (int j = 0; j < 4; j++) {
            int4 rr = (j == 0) ? r0 : (j == 1) ? r1 : (j == 2) ? r2 : r3;
            Half4 hh = (j == 0) ? hv0 : (j == 1) ? hv1 : (j == 2) ? hv2 : hv3;
            float2 c01 = __half22float2(int_as_h2(rr.y));
            float2 c23 = __half22float2(int_as_h2(rr.z));
            float2 lo = __half22float2(hh.lo), hi = __half22float2(hh.hi);
            a0.x += c01.x * lo.x; a0.y += c01.x * lo.y; a0.z += c01.x * hi.x; a0.w += c01.x * hi.y;
            a1.x += c01.y * lo.x; a1.y += c01.y * lo.y; a1.z += c01.y * hi.x; a1.w += c01.y * hi.y;
            a2.x += c23.x * lo.x; a2.y += c23.x * lo.y; a2.z += c23.x * hi.x; a2.w += c23.x * hi.y;
            a3.x += c23.y * lo.x; a3.y += c23.y * lo.y; a3.z += c23.y * hi.x; a3.w += c23.y * hi.y;
        }
    }
    for (; i < deg; i++) {
        int4 rr = g_edge[base + i];
        Half4 hh = *(const Half4*)(Hl + (size_t)rr.x * HD);
        float2 c01 = __half22float2(int_as_h2(rr.y));
        float2 c23 = __half22float2(int_as_h2(rr.z));
        float2 lo = __half22float2(hh.lo), hi = __half22float2(hh.hi);
        a0.x += c01.x * lo.x; a0.y += c01.x * lo.y; a0.z += c01.x * hi.x; a0.w += c01.x * hi.y;
        a1.x += c01.y * lo.x; a1.y += c01.y * lo.y; a1.z += c01.y * hi.x; a1.w += c01.y * hi.y;
        a2.x += c23.x * lo.x; a2.y += c23.x * lo.y; a2.z += c23.x * hi.x; a2.w += c23.x * hi.y;
        a3.x += c23.y * lo.x; a3.y += c23.y * lo.y; a3.z += c23.y * hi.x; a3.w += c23.y * hi.y;
    }

    __half* ap = g_agg + (size_t)v * 512 + lane * 4;
    Half4 o;
    o.lo = __floats2half2_rn(a0.x, a0.y); o.hi = __floats2half2_rn(a0.z, a0.w);
    *(Half4*)(ap + 0)   = o;
    o.lo = __floats2half2_rn(a1.x, a1.y); o.hi = __floats2half2_rn(a1.z, a1.w);
    *(Half4*)(ap + 128) = o;
    o.lo = __floats2half2_rn(a2.x, a2.y); o.hi = __floats2half2_rn(a2.z, a2.w);
    *(Half4*)(ap + 256) = o;
    o.lo = __floats2half2_rn(a3.x, a3.y); o.hi = __floats2half2_rn(a3.z, a3.w);
    *(Half4*)(ap + 384) = o;
}

// ---------------------------------------------------------------------------
// gemm2: fp16 mma m16n8k16, 3-stage cp.async pipeline, 2 blocks/SM.
// Block 128m x 128n, K=640 in 64-chunks; 8 warps = 4m x 2n.
// ---------------------------------------------------------------------------
#define STAGE_HALVES (2 * 128 * SMSH)              // A + B per stage
#define STAGE_BYTES  (STAGE_HALVES * 2)            // 36864
#define SMEM_BYTES   (3 * STAGE_BYTES)             // 110592 (x2 blocks = 221KB <= 228KB)

__global__ __launch_bounds__(256, 2) void gemm2_k(
    const float* __restrict__ bias,
    float* __restrict__ out,
    int M)
{
    extern __shared__ __half smh[];

    const int tid  = threadIdx.x;
    const int m0   = blockIdx.x * 128;
    const int lane = tid & 31;
    const int w    = tid >> 5;
    const int wm   = w & 3;
    const int wn   = w >> 2;

    const int fr = tid >> 4;     // 0..15 base row, step 16
    const int fq = tid & 15;     // Half4 quad in 64-half chunk row

    uint32_t sA0 = smem_u32(smh) + (uint32_t)(fr * SMSH + fq * 4) * 2;
    uint32_t sB0 = sA0 + (uint32_t)(128 * SMSH) * 2;

    auto fill = [&](int kc, int s) {
        uint32_t sa = sA0 + s * STAGE_BYTES;
        uint32_t sb = sB0 + s * STAGE_BYTES;
        if (kc < 8) {
            const __half* ap = g_agg + (size_t)(m0 + fr) * 512 + kc * 64 + fq * 4;
            #pragma unroll
            for (int i = 0; i < 8; i++)
                CP_ASYNC8(sa + i * 16 * SMSH * 2, ap + (size_t)i * 16 * 512);
        } else {
            const __half* ap = g_h16 + (size_t)(m0 + fr) * HD + (kc * 64 - 512) + fq * 4;
            #pragma unroll
            for (int i = 0; i < 8; i++)
                CP_ASYNC8(sa + i * 16 * SMSH * 2, ap + (size_t)i * 16 * HD);
        }
        const __half* bp = g_Wh + (size_t)fr * KTOT + kc * 64 + fq * 4;
        #pragma unroll
        for (int i = 0; i < 8; i++)
            CP_ASYNC8(sb + i * 16 * SMSH * 2, bp + (size_t)i * 16 * KTOT);
        CP_COMMIT();
    };

    const int arow  = (lane & 7) + ((lane >> 3) & 1) * 8;
    const int akoff = (lane & 16) ? 8 : 0;
    const int brow  = (lane & 7) + ((lane & 16) ? 8 : 0);
    const int bkoff = (lane & 8) ? 8 : 0;

    uint32_t aAddr[2], bAddr[4];
    #pragma unroll
    for (int mt = 0; mt < 2; mt++)
        aAddr[mt] = smem_u32(smh + (wm * 32 + mt * 16 + arow) * SMSH + akoff);
    #pragma unroll
    for (int p = 0; p < 4; p++)
        bAddr[p] = smem_u32(smh + 128 * SMSH + (wn * 64 + p * 16 + brow) * SMSH + bkoff);

    float acc[2][8][4];
    #pragma unroll
    for (int mt = 0; mt < 2; mt++)
        #pragma unroll
        for (int nt = 0; nt < 8; nt++)
            #pragma unroll
            for (int q = 0; q < 4; q++) acc[mt][nt][q] = 0.f;

    fill(0, 0);
    fill(1, 1);
    fill(2, 2);

    for (int kc = 0; kc < 10; kc++) {
        int s = kc % 3;
        if (kc < 8)       { asm volatile("cp.async.wait_group 2;"); }
        else if (kc == 8) { asm volatile("cp.async.wait_group 1;"); }
        else              { asm volatile("cp.async.wait_group 0;"); }
        __syncthreads();

        uint32_t soff = (uint32_t)s * STAGE_BYTES;
        #pragma unroll
        for (int k0 = 0; k0 < 64; k0 += 16) {
            uint32_t a[2][4], b[4][4];
            #pragma unroll
            for (int mt = 0; mt < 2; mt++)
                asm volatile("ldmatrix.sync.aligned.m8n8.x4.shared.b16 {%0,%1,%2,%3}, [%4];"
                             : "=r"(a[mt][0]), "=r"(a[mt][1]), "=r"(a[mt][2]), "=r"(a[mt][3])
                             : "r"(aAddr[mt] + soff + k0 * 2));
            #pragma unroll
            for (int p = 0; p < 4; p++)
                asm volatile("ldmatrix.sync.aligned.m8n8.x4.shared.b16 {%0,%1,%2,%3}, [%4];"
                             : "=r"(b[p][0]), "=r"(b[p][1]), "=r"(b[p][2]), "=r"(b[p][3])
                             : "r"(bAddr[p] + soff + k0 * 2));
            #pragma unroll
            for (int mt = 0; mt < 2; mt++)
                #pragma unroll
                for (int nt = 0; nt < 8; nt++) {
                    int p = nt >> 1, q = (nt & 1) * 2;
                    asm volatile(
                        "mma.sync.aligned.m16n8k16.row.col.f32.f16.f16.f32 "
                        "{%0,%1,%2,%3}, {%4,%5,%6,%7}, {%8,%9}, {%0,%1,%2,%3};"
                        : "+f"(acc[mt][nt][0]), "+f"(acc[mt][nt][1]),
                          "+f"(acc[mt][nt][2]), "+f"(acc[mt][nt][3])
                        : "r"(a[mt][0]), "r"(a[mt][1]), "r"(a[mt][2]), "r"(a[mt][3]),
                          "r"(b[p][q]), "r"(b[p][q + 1]));
                }
        }
        __syncthreads();
        if (kc + 3 < 10) fill(kc + 3, s);
    }

    // ---- epilogue: bias + relu ----
    const int rbase = lane >> 2;
    const int col2  = (lane & 3) * 2;
    #pragma unroll
    for (int mt = 0; mt < 2; mt++) {
        #pragma unroll
        for (int hh = 0; hh < 2; hh++) {
            int gm = m0 + wm * 32 + mt * 16 + rbase + hh * 8;
            if (gm >= M) continue;
            #pragma unroll
            for (int nt = 0; nt < 8; nt++) {
                int gn = wn * 64 + nt * 8 + col2;
                float2 o;
                o.x = fmaxf(acc[mt][nt][hh * 2]     + bias[gn],     0.f);
                o.y = fmaxf(acc[mt][nt][hh * 2 + 1] + bias[gn + 1], 0.f);
                *(float2*)(out + (size_t)gm * HD + gn) = o;
            }
        }
    }
}

extern "C" void kernel_launch(void* const* d_in, const int* in_sizes, int n_in,
                              void* d_out, int out_size)
{
    const float* h       = (const float*)d_in[0];
    const float* norm    = (const float*)d_in[1];
    const float* basis_w = (const float*)d_in[2];
    const float* w_comp  = (const float*)d_in[3];
    const float* loop_w  = (const float*)d_in[4];
    const float* bias    = (const float*)d_in[5];
    const int*   src     = (const int*)d_in[6];
    const int*   dst     = (const int*)d_in[7];
    const int*   etype   = (const int*)d_in[8];
    float* out = (float*)d_out;

    int M = in_sizes[0] / HD;   // 50000
    int E = in_sizes[6];        // 800000

    cudaFuncSetAttribute(gemm2_k, cudaFuncAttributeMaxDynamicSharedMemorySize, SMEM_BYTES);

    prep_k<<<(NP * 32 + 255) / 256, 256>>>(h, basis_w, loop_w, M);
    hist_k<<<((E + 3) / 4 + 255) / 256, 256>>>(dst, E);
    scan_k<<<NBLK, 256>>>();
    bucket_k<<<((E + 3) / 4 + 255) / 256, 256>>>(w_comp, norm, src, dst, etype, E);
    accum_k<<<(NP * 32 + 255) / 256, 256>>>();
    gemm2_k<<<NP / 128, 256, SMEM_BYTES>>>(bias, out, M);
}